// round 12
// baseline (speedup 1.0000x reference)
#include <cuda_runtime.h>
#include <cstdint>

#define BB 16
#define SS 2048
#define DD 512
#define NGRP 4                     // batch groups for pipeline overlap
#define GB (BB / NGRP)             // batches per group (4)
#define NST 5                      // cp.async ring stages
#define ROWSTR 16                  // smem row stride in floats (x4-perm -> conflict-free LDS.128)
#define STAGE_F (128 * ROWSTR)     // floats per 16-k stage per operand (2048 = 8KB)

// ---------------- device scratch ----------------
__device__ float g_a[BB * SS];
__device__ float g_c[BB * SS];
__device__ int   g_segstart[BB * (SS + 1)];
__device__ int   g_nwords[BB];
__device__ float g_mean[(size_t)BB * SS * DD];   // tf32-rounded, x4-k-permuted means
__device__ float g_wcT[DD * DD];                 // w_comb^T [N][K], tf32-rounded, permuted

__device__ __forceinline__ uint32_t f2tf32(float v) {
    uint32_t r;
    asm("cvt.rna.tf32.f32 %0, %1;" : "=r"(r) : "f"(v));
    return r;
}
__device__ __forceinline__ uint32_t smem_u32(const void* p) {
    uint32_t a;
    asm("{ .reg .u64 t; cvta.to.shared.u64 t, %1; cvt.u32.u64 %0, t; }" : "=r"(a) : "l"(p));
    return a;
}
#define CP16(dst, src) \
    asm volatile("cp.async.cg.shared.global [%0], [%1], 16;" :: "r"(dst), "l"(src))
#define CP_COMMIT() asm volatile("cp.async.commit_group;" ::: "memory")
#define CP_WAIT1()  asm volatile("cp.async.wait_group 1;" ::: "memory")

__device__ __forceinline__ void mma_tf32(float c[4], uint32_t a0, uint32_t a1,
                                         uint32_t a2, uint32_t a3,
                                         uint32_t b0, uint32_t b1) {
    asm volatile(
        "mma.sync.aligned.m16n8k8.row.col.f32.tf32.tf32.f32 "
        "{%0,%1,%2,%3}, {%4,%5,%6,%7}, {%8,%9}, {%0,%1,%2,%3};"
        : "+f"(c[0]), "+f"(c[1]), "+f"(c[2]), "+f"(c[3])
        : "r"(a0), "r"(a1), "r"(a2), "r"(a3), "r"(b0), "r"(b1));
}

// ---------------- K1: per-frame score dots (2 rows per warp), batch-group --------
__global__ void k_scores(const float* __restrict__ frame, const float* __restrict__ wscore,
                         int b0) {
    int warp = (blockIdx.x * blockDim.x + threadIdx.x) >> 5;
    int lane = threadIdx.x & 31;
    if (warp >= GB * SS / 2) return;
    int row = b0 * SS + warp * 2;
    const float4* r0 = (const float4*)(frame + (size_t)row * DD);
    const float4* r1 = (const float4*)(frame + (size_t)(row + 1) * DD);
    const float4* w1 = (const float4*)wscore;
    const float4* w2 = (const float4*)(wscore + DD);
    float d1a = 0.f, d2a = 0.f, d1b = 0.f, d2b = 0.f;
#pragma unroll
    for (int k = 0; k < 4; k++) {
        int i = lane + k * 32;
        float4 f0 = r0[i];
        float4 f1 = r1[i];
        float4 a = w1[i];
        float4 b = w2[i];
        d1a += f0.x * a.x + f0.y * a.y + f0.z * a.z + f0.w * a.w;
        d2a += f0.x * b.x + f0.y * b.y + f0.z * b.z + f0.w * b.w;
        d1b += f1.x * a.x + f1.y * a.y + f1.z * a.z + f1.w * a.w;
        d2b += f1.x * b.x + f1.y * b.y + f1.z * b.z + f1.w * b.w;
    }
#pragma unroll
    for (int off = 16; off; off >>= 1) {
        d1a += __shfl_down_sync(0xFFFFFFFFu, d1a, off);
        d2a += __shfl_down_sync(0xFFFFFFFFu, d2a, off);
        d1b += __shfl_down_sync(0xFFFFFFFFu, d1b, off);
        d2b += __shfl_down_sync(0xFFFFFFFFu, d2b, off);
    }
    if (lane == 0) {
        g_a[row] = d1a;     g_c[row] = d2a;
        g_a[row + 1] = d1b; g_c[row + 1] = d2b;
    }
}

// ---------------- K2: per-batch segment scan, batch-group ----------------
__global__ void k_scan(const float* __restrict__ bscore_p, float* __restrict__ out_tail,
                       int b0) {
    int b   = b0 + blockIdx.x;
    int tid = threadIdx.x;
    float bs = *bscore_p;
    int t0 = tid * 2, t1 = t0 + 1;
    int s0 = (t0 == 0) ? 0
             : (((g_a[b * SS + t0 - 1] + g_c[b * SS + t0] + bs) > 0.5f) ? 0 : 1);
    int s1 = (((g_a[b * SS + t1 - 1] + g_c[b * SS + t1] + bs) > 0.5f) ? 0 : 1);

    __shared__ int sc[1024];
    sc[tid] = s0 + s1;
    __syncthreads();
    for (int off = 1; off < 1024; off <<= 1) {
        int v   = sc[tid];
        int add = (tid >= off) ? sc[tid - off] : 0;
        __syncthreads();
        sc[tid] = v + add;
        __syncthreads();
    }
    int excl = (tid == 0) ? 0 : sc[tid - 1];
    int seg0 = excl + s0;
    int seg1 = excl + s0 + s1;

    int base = b * (SS + 1);
    if (t0 == 0 || s0 == 1) g_segstart[base + seg0] = t0;
    if (s1 == 1)            g_segstart[base + seg1] = t1;
    if (t1 == SS - 1) {
        int nw = seg1 + 1;
        g_nwords[b] = nw;
        g_segstart[base + nw] = SS;
        if (out_tail) out_tail[b] = (float)nw;
    }
}

// ---------------- K3: segment means (tf32, x4-k-permuted), batch-group -----------
__global__ void k_mean(const float* __restrict__ frame, int b0) {
    int j = b0 * SS + blockIdx.x * 2 + (threadIdx.x >> 5);
    int lane = threadIdx.x & 31;
    int b = j / SS, w = j % SS;
    if (w >= g_nwords[b]) return;
    int base = b * (SS + 1);
    int st = g_segstart[base + w];
    int en = g_segstart[base + w + 1];
    float inv = 1.0f / (float)(en - st);
    float a[16];
#pragma unroll
    for (int i = 0; i < 16; i++) a[i] = 0.f;
    int t = st;
    for (; t + 1 < en; t += 2) {
        const float4* p0 = (const float4*)(frame + ((size_t)(b * SS + t)) * DD + lane * 16);
        const float4* p1 = (const float4*)(frame + ((size_t)(b * SS + t + 1)) * DD + lane * 16);
        float4 u0 = p0[0], u1 = p0[1], u2 = p0[2], u3 = p0[3];
        float4 v0 = p1[0], v1 = p1[1], v2 = p1[2], v3 = p1[3];
        a[0] += u0.x;  a[1] += u0.y;  a[2] += u0.z;  a[3] += u0.w;
        a[4] += u1.x;  a[5] += u1.y;  a[6] += u1.z;  a[7] += u1.w;
        a[8] += u2.x;  a[9] += u2.y;  a[10] += u2.z; a[11] += u2.w;
        a[12] += u3.x; a[13] += u3.y; a[14] += u3.z; a[15] += u3.w;
        a[0] += v0.x;  a[1] += v0.y;  a[2] += v0.z;  a[3] += v0.w;
        a[4] += v1.x;  a[5] += v1.y;  a[6] += v1.z;  a[7] += v1.w;
        a[8] += v2.x;  a[9] += v2.y;  a[10] += v2.z; a[11] += v2.w;
        a[12] += v3.x; a[13] += v3.y; a[14] += v3.z; a[15] += v3.w;
    }
    if (t < en) {
        const float4* p = (const float4*)(frame + ((size_t)(b * SS + t)) * DD + lane * 16);
#pragma unroll
        for (int q = 0; q < 4; q++) {
            float4 v = p[q];
            a[q * 4 + 0] += v.x; a[q * 4 + 1] += v.y;
            a[q * 4 + 2] += v.z; a[q * 4 + 3] += v.w;
        }
    }
    uint4* dst = (uint4*)(g_mean + (size_t)j * DD + lane * 16);
#pragma unroll
    for (int q = 0; q < 4; q++) {
        uint4 o;
        o.x = f2tf32(a[q] * inv);
        o.y = f2tf32(a[q + 4] * inv);
        o.z = f2tf32(a[q + 8] * inv);
        o.w = f2tf32(a[q + 12] * inv);
        dst[q] = o;
    }
}

// ---------------- K3b: w_comb -> g_wcT[N][K] transposed, rounded, x4-permuted ------
__global__ void k_wcT(const float* __restrict__ wc) {
    __shared__ float t[32][33];
    int k0 = blockIdx.y * 32, n0 = blockIdx.x * 32;
    int x = threadIdx.x, y0 = threadIdx.y;     // 32 x 8
#pragma unroll
    for (int dy = 0; dy < 32; dy += 8)
        t[y0 + dy][x] = wc[(size_t)(k0 + y0 + dy) * DD + n0 + x];
    __syncthreads();
#pragma unroll
    for (int dy = 0; dy < 32; dy += 8) {
        int k = k0 + x;
        int kp = (k & ~15) | (4 * (k & 3)) | ((k >> 2) & 3);
        g_wcT[(size_t)(n0 + y0 + dy) * DD + kp] =
            __uint_as_float(f2tf32(t[x][y0 + dy]));
    }
}

// ---------------- K4: tf32 mma.sync GEMM (R10 body), batch-group ------------------
__global__ void __launch_bounds__(256, 2)
k_gemm_tc(const float* __restrict__ bc, float* __restrict__ out, int b0) {
    int b    = b0 + blockIdx.z;
    int row0 = blockIdx.y * 128;
    int col0 = blockIdx.x * 128;
    int nw   = g_nwords[b];
    int tid  = threadIdx.x;
    float* outbase = out + (size_t)b * SS * DD;

    if (row0 >= nw) {
        float4 z = make_float4(0.f, 0.f, 0.f, 0.f);
        for (int i = tid; i < 128 * 32; i += 256) {
            int r = i >> 5, cq = i & 31;
            ((float4*)(outbase + (size_t)(row0 + r) * DD + col0))[cq] = z;
        }
        return;
    }

    extern __shared__ float sm[];
    float* AsB = sm;                          // NST * STAGE_F
    float* BsB = sm + NST * STAGE_F;

    const float* A  = g_mean + ((size_t)b * SS + row0) * DD;
    const float* Bm = g_wcT + (size_t)col0 * DD;

    uint32_t aA = smem_u32(AsB), aB = smem_u32(BsB);
    int r0c = tid >> 2, c0c = tid & 3;
    int r1c = (tid + 256) >> 2, c1c = (tid + 256) & 3;
    uint32_t d0 = (uint32_t)r0c * 64 + (uint32_t)c0c * 16;
    uint32_t d1 = (uint32_t)r1c * 64 + (uint32_t)c1c * 16;

    int wid  = tid >> 5;
    int lane = tid & 31;
    int wm   = wid & 3;
    int wn   = wid >> 2;
    int gid  = lane >> 2;
    int tq   = lane & 3;

    float acc[2][8][4];
#pragma unroll
    for (int mt = 0; mt < 2; mt++)
#pragma unroll
        for (int nt = 0; nt < 8; nt++)
#pragma unroll
            for (int i = 0; i < 4; i++) acc[mt][nt][i] = 0.f;

#pragma unroll
    for (int p = 0; p < 3; p++) {
        uint32_t sb = p * (STAGE_F * 4);
        CP16(aA + sb + d0, A + (size_t)r0c * DD + p * 16 + c0c * 4);
        CP16(aA + sb + d1, A + (size_t)r1c * DD + p * 16 + c1c * 4);
        CP16(aB + sb + d0, Bm + (size_t)r0c * DD + p * 16 + c0c * 4);
        CP16(aB + sb + d1, Bm + (size_t)r1c * DD + p * 16 + c1c * 4);
        CP_COMMIT();
    }

    const int NKT = DD / 16;
    for (int kt = 0; kt < NKT; kt += 2) {
        CP_WAIT1();
        __syncthreads();

#pragma unroll
        for (int e = 3; e <= 4; e++) {
            int p = kt + e;
            if (p < NKT) {
                uint32_t sb = (uint32_t)(p % NST) * (STAGE_F * 4);
                CP16(aA + sb + d0, A + (size_t)r0c * DD + p * 16 + c0c * 4);
                CP16(aA + sb + d1, A + (size_t)r1c * DD + p * 16 + c1c * 4);
                CP16(aB + sb + d0, Bm + (size_t)r0c * DD + p * 16 + c0c * 4);
                CP16(aB + sb + d1, Bm + (size_t)r1c * DD + p * 16 + c1c * 4);
            }
            CP_COMMIT();
        }

#pragma unroll
        for (int h = 0; h < 2; h++) {
            int s = (kt + h) % NST;
            const float* as = AsB + s * STAGE_F;
            const float* bs = BsB + s * STAGE_F;

            float4 pa[2][2];
#pragma unroll
            for (int mt = 0; mt < 2; mt++) {
                int rb = wm * 32 + mt * 16 + gid;
                pa[mt][0] = *(const float4*)(as + rb * ROWSTR + 4 * tq);
                pa[mt][1] = *(const float4*)(as + (rb + 8) * ROWSTR + 4 * tq);
            }
#pragma unroll
            for (int bg = 0; bg < 2; bg++) {
                float4 pb[4];
#pragma unroll
                for (int jj = 0; jj < 4; jj++) {
                    int nb = wn * 64 + (bg * 4 + jj) * 8 + gid;
                    pb[jj] = *(const float4*)(bs + nb * ROWSTR + 4 * tq);
                }
#pragma unroll
                for (int mt = 0; mt < 2; mt++)
#pragma unroll
                    for (int jj = 0; jj < 4; jj++) {
                        int nt = bg * 4 + jj;
                        mma_tf32(acc[mt][nt],
                                 __float_as_uint(pa[mt][0].x), __float_as_uint(pa[mt][1].x),
                                 __float_as_uint(pa[mt][0].y), __float_as_uint(pa[mt][1].y),
                                 __float_as_uint(pb[jj].x), __float_as_uint(pb[jj].y));
                        mma_tf32(acc[mt][nt],
                                 __float_as_uint(pa[mt][0].z), __float_as_uint(pa[mt][1].z),
                                 __float_as_uint(pa[mt][0].w), __float_as_uint(pa[mt][1].w),
                                 __float_as_uint(pb[jj].z), __float_as_uint(pb[jj].w));
                    }
            }
        }
    }

#pragma unroll
    for (int mt = 0; mt < 2; mt++) {
        int r0g = row0 + wm * 32 + mt * 16 + gid;
        int r1g = r0g + 8;
#pragma unroll
        for (int nt = 0; nt < 8; nt++) {
            int col = col0 + wn * 64 + nt * 8 + 2 * tq;
            float2 bias = *(const float2*)(bc + col);
            float2 v0, v1;
            if (r0g < nw) {
                v0.x = acc[mt][nt][0] + bias.x;
                v0.y = acc[mt][nt][1] + bias.y;
            } else { v0.x = 0.f; v0.y = 0.f; }
            if (r1g < nw) {
                v1.x = acc[mt][nt][2] + bias.x;
                v1.y = acc[mt][nt][3] + bias.y;
            } else { v1.x = 0.f; v1.y = 0.f; }
            *(float2*)(outbase + (size_t)r0g * DD + col) = v0;
            *(float2*)(outbase + (size_t)r1g * DD + col) = v1;
        }
    }
}

// ---------------- launcher: 2-stream fork-join pipeline over 4 batch groups -------
extern "C" void kernel_launch(void* const* d_in, const int* in_sizes, int n_in,
                              void* d_out, int out_size) {
    const float* frame  = (const float*)d_in[0];   // [B,S,D]
    const float* wscore = (const float*)d_in[1];   // [2D,1]
    const float* bscore = (const float*)d_in[2];   // [1]
    const float* wcomb  = (const float*)d_in[3];   // [D,D]
    const float* bcomb  = (const float*)d_in[4];   // [D]
    float* out = (float*)d_out;

    float* tail = (out_size >= BB * SS * DD + BB) ? out + (size_t)BB * SS * DD : nullptr;

    // created once on the (uncaptured) correctness call; reused under capture
    static cudaStream_t s_side = nullptr;
    static cudaEvent_t  evFork = nullptr;
    static cudaEvent_t  evGrp[NGRP];
    static bool s_attr = false;
    const int SMEM_DYN = 2 * NST * STAGE_F * 4;    // 80 KB
    if (!s_side) {
        cudaStreamCreateWithFlags(&s_side, cudaStreamNonBlocking);
        cudaEventCreateWithFlags(&evFork, cudaEventDisableTiming);
        for (int g = 0; g < NGRP; g++)
            cudaEventCreateWithFlags(&evGrp[g], cudaEventDisableTiming);
    }
    if (!s_attr) {
        cudaFuncSetAttribute(k_gemm_tc, cudaFuncAttributeMaxDynamicSharedMemorySize, SMEM_DYN);
        s_attr = true;
    }

    // main stream: weight transpose (needed by every gemm group)
    k_wcT<<<dim3(DD / 32, DD / 32), dim3(32, 8)>>>(wcomb);

    // fork side stream off main
    cudaEventRecord(evFork, 0);
    cudaStreamWaitEvent(s_side, evFork, 0);

    // side stream: per-group prep (scores -> scan -> mean), signal per group
    for (int g = 0; g < NGRP; g++) {
        int b0 = g * GB;
        k_scores<<<(GB * SS) / 16, 256, 0, s_side>>>(frame, wscore, b0);
        k_scan<<<GB, 1024, 0, s_side>>>(bscore, tail, b0);
        k_mean<<<(GB * SS) / 2, 64, 0, s_side>>>(frame, b0);
        cudaEventRecord(evGrp[g], s_side);
    }

    // main stream: per-group GEMM, gated on that group's prep
    for (int g = 0; g < NGRP; g++) {
        cudaStreamWaitEvent(0, evGrp[g], 0);
        dim3 grid(DD / 128, SS / 128, GB);
        k_gemm_tc<<<grid, 256, SMEM_DYN>>>(bcomb, out, g * GB);
    }
}

// round 14
// speedup vs baseline: 1.3277x; 1.3277x over previous
#include <cuda_runtime.h>
#include <cstdint>

#define BB 16
#define SS 2048
#define DD 512
#define NST 4                      // cp.async pipeline stages
#define ROWSTR 16                  // smem row stride in floats (x4-perm -> conflict-free LDS.128)
#define STAGE_F (128 * ROWSTR)     // floats per 16-k stage per operand (2048 = 8KB)

// ---------------- device scratch ----------------
__device__ float g_a[BB * SS];
__device__ float g_c[BB * SS];
__device__ int   g_segstart[BB * (SS + 1)];
__device__ int   g_nwords[BB];
__device__ float g_mean[(size_t)BB * SS * DD];   // tf32-rounded, x4-k-permuted means
__device__ float g_wcT[DD * DD];                 // w_comb^T [N][K], tf32-rounded, permuted

__device__ __forceinline__ uint32_t f2tf32(float v) {
    uint32_t r;
    asm("cvt.rna.tf32.f32 %0, %1;" : "=r"(r) : "f"(v));
    return r;
}
__device__ __forceinline__ uint32_t smem_u32(const void* p) {
    uint32_t a;
    asm("{ .reg .u64 t; cvta.to.shared.u64 t, %1; cvt.u32.u64 %0, t; }" : "=r"(a) : "l"(p));
    return a;
}
#define CP16(dst, src) \
    asm volatile("cp.async.cg.shared.global [%0], [%1], 16;" :: "r"(dst), "l"(src))
#define CP_COMMIT() asm volatile("cp.async.commit_group;" ::: "memory")
#define CP_WAIT2()  asm volatile("cp.async.wait_group 2;" ::: "memory")

__device__ __forceinline__ void mma_tf32(float c[4], uint32_t a0, uint32_t a1,
                                         uint32_t a2, uint32_t a3,
                                         uint32_t b0, uint32_t b1) {
    asm volatile(
        "mma.sync.aligned.m16n8k8.row.col.f32.tf32.tf32.f32 "
        "{%0,%1,%2,%3}, {%4,%5,%6,%7}, {%8,%9}, {%0,%1,%2,%3};"
        : "+f"(c[0]), "+f"(c[1]), "+f"(c[2]), "+f"(c[3])
        : "r"(a0), "r"(a1), "r"(a2), "r"(a3), "r"(b0), "r"(b1));
}

// ---------------- K1: fused weight-transpose + per-frame score dots ----------------
// blocks [0,256): w_comb -> g_wcT (transposed, tf32-rounded, x4-permuted)
// blocks [256, 256+2048): score dots, 2 rows per warp
__global__ void k_prep(const float* __restrict__ frame, const float* __restrict__ wscore,
                       const float* __restrict__ wc) {
    int bx = blockIdx.x;
    if (bx < 256) {
        __shared__ float t[32][33];
        int n0 = (bx & 15) * 32, k0 = (bx >> 4) * 32;
        int x = threadIdx.x & 31, y0 = threadIdx.x >> 5;   // 32 x 8
#pragma unroll
        for (int dy = 0; dy < 32; dy += 8)
            t[y0 + dy][x] = wc[(size_t)(k0 + y0 + dy) * DD + n0 + x];
        __syncthreads();
#pragma unroll
        for (int dy = 0; dy < 32; dy += 8) {
            int k = k0 + x;
            int kp = (k & ~15) | (4 * (k & 3)) | ((k >> 2) & 3);
            g_wcT[(size_t)(n0 + y0 + dy) * DD + kp] =
                __uint_as_float(f2tf32(t[x][y0 + dy]));
        }
        return;
    }
    int warp = (bx - 256) * 8 + (threadIdx.x >> 5);
    int lane = threadIdx.x & 31;
    if (warp >= BB * SS / 2) return;
    int row = warp * 2;
    const float4* r0 = (const float4*)(frame + (size_t)row * DD);
    const float4* r1 = (const float4*)(frame + (size_t)(row + 1) * DD);
    const float4* w1 = (const float4*)wscore;
    const float4* w2 = (const float4*)(wscore + DD);
    float d1a = 0.f, d2a = 0.f, d1b = 0.f, d2b = 0.f;
#pragma unroll
    for (int k = 0; k < 4; k++) {
        int i = lane + k * 32;
        float4 f0 = r0[i];
        float4 f1 = r1[i];
        float4 a = w1[i];
        float4 b = w2[i];
        d1a += f0.x * a.x + f0.y * a.y + f0.z * a.z + f0.w * a.w;
        d2a += f0.x * b.x + f0.y * b.y + f0.z * b.z + f0.w * b.w;
        d1b += f1.x * a.x + f1.y * a.y + f1.z * a.z + f1.w * a.w;
        d2b += f1.x * b.x + f1.y * b.y + f1.z * b.z + f1.w * b.w;
    }
#pragma unroll
    for (int off = 16; off; off >>= 1) {
        d1a += __shfl_down_sync(0xFFFFFFFFu, d1a, off);
        d2a += __shfl_down_sync(0xFFFFFFFFu, d2a, off);
        d1b += __shfl_down_sync(0xFFFFFFFFu, d1b, off);
        d2b += __shfl_down_sync(0xFFFFFFFFu, d2b, off);
    }
    if (lane == 0) {
        g_a[row] = d1a;     g_c[row] = d2a;
        g_a[row + 1] = d1b; g_c[row + 1] = d2b;
    }
}

// ---------------- K2: per-batch segment scan ----------------
__global__ void k_scan(const float* __restrict__ bscore_p, float* __restrict__ out_tail) {
    int b   = blockIdx.x;
    int tid = threadIdx.x;
    float bs = *bscore_p;
    int t0 = tid * 2, t1 = t0 + 1;
    int s0 = (t0 == 0) ? 0
             : (((g_a[b * SS + t0 - 1] + g_c[b * SS + t0] + bs) > 0.5f) ? 0 : 1);
    int s1 = (((g_a[b * SS + t1 - 1] + g_c[b * SS + t1] + bs) > 0.5f) ? 0 : 1);

    __shared__ int sc[1024];
    sc[tid] = s0 + s1;
    __syncthreads();
    for (int off = 1; off < 1024; off <<= 1) {
        int v   = sc[tid];
        int add = (tid >= off) ? sc[tid - off] : 0;
        __syncthreads();
        sc[tid] = v + add;
        __syncthreads();
    }
    int excl = (tid == 0) ? 0 : sc[tid - 1];
    int seg0 = excl + s0;
    int seg1 = excl + s0 + s1;

    int base = b * (SS + 1);
    if (t0 == 0 || s0 == 1) g_segstart[base + seg0] = t0;
    if (s1 == 1)            g_segstart[base + seg1] = t1;
    if (t1 == SS - 1) {
        int nw = seg1 + 1;
        g_nwords[b] = nw;
        g_segstart[base + nw] = SS;
        if (out_tail) out_tail[b] = (float)nw;
    }
}

// ---------------- K3: segment means (tf32, x4-k-permuted), 8 words/block ----------
__global__ void k_mean(const float* __restrict__ frame) {
    int j = blockIdx.x * 8 + (threadIdx.x >> 5);   // word index
    int lane = threadIdx.x & 31;
    int b = j / SS, w = j % SS;
    if (w >= g_nwords[b]) return;
    int base = b * (SS + 1);
    int st = g_segstart[base + w];
    int en = g_segstart[base + w + 1];
    float inv = 1.0f / (float)(en - st);
    float a[16];
#pragma unroll
    for (int i = 0; i < 16; i++) a[i] = 0.f;
    for (int t = st; t < en; t++) {
        const float4* p = (const float4*)(frame + ((size_t)(b * SS + t)) * DD + lane * 16);
#pragma unroll
        for (int q = 0; q < 4; q++) {
            float4 v = p[q];
            a[q * 4 + 0] += v.x; a[q * 4 + 1] += v.y;
            a[q * 4 + 2] += v.z; a[q * 4 + 3] += v.w;
        }
    }
    uint4* dst = (uint4*)(g_mean + (size_t)j * DD + lane * 16);
#pragma unroll
    for (int q = 0; q < 4; q++) {
        uint4 o;
        o.x = f2tf32(a[q] * inv);
        o.y = f2tf32(a[q + 4] * inv);
        o.z = f2tf32(a[q + 8] * inv);
        o.w = f2tf32(a[q + 12] * inv);
        dst[q] = o;
    }
}

// ---------------- K4: tf32 mma.sync GEMM (R10 body, unchanged) --------------------
__global__ void __launch_bounds__(256, 2)
k_gemm_tc(const float* __restrict__ bc, float* __restrict__ out) {
    int b    = blockIdx.z;
    int row0 = blockIdx.y * 128;
    int col0 = blockIdx.x * 128;
    int nw   = g_nwords[b];
    int tid  = threadIdx.x;
    float* outbase = out + (size_t)b * SS * DD;

    if (row0 >= nw) {
        float4 z = make_float4(0.f, 0.f, 0.f, 0.f);
        for (int i = tid; i < 128 * 32; i += 256) {
            int r = i >> 5, cq = i & 31;
            ((float4*)(outbase + (size_t)(row0 + r) * DD + col0))[cq] = z;
        }
        return;
    }

    extern __shared__ float sm[];
    float* AsB = sm;                          // NST * STAGE_F
    float* BsB = sm + NST * STAGE_F;

    const float* A  = g_mean + ((size_t)b * SS + row0) * DD;
    const float* Bm = g_wcT + (size_t)col0 * DD;

    uint32_t aA = smem_u32(AsB), aB = smem_u32(BsB);
    int r0c = tid >> 2, c0c = tid & 3;
    int r1c = (tid + 256) >> 2, c1c = (tid + 256) & 3;
    uint32_t d0 = (uint32_t)r0c * 64 + (uint32_t)c0c * 16;
    uint32_t d1 = (uint32_t)r1c * 64 + (uint32_t)c1c * 16;

    int wid  = tid >> 5;
    int lane = tid & 31;
    int wm   = wid & 3;                       // warp row (x32)
    int wn   = wid >> 2;                      // warp col (x64)
    int gid  = lane >> 2;
    int tq   = lane & 3;

    float acc[2][8][4];
#pragma unroll
    for (int mt = 0; mt < 2; mt++)
#pragma unroll
        for (int nt = 0; nt < 8; nt++)
#pragma unroll
            for (int i = 0; i < 4; i++) acc[mt][nt][i] = 0.f;

#pragma unroll
    for (int p = 0; p < 3; p++) {
        uint32_t sb = p * (STAGE_F * 4);
        CP16(aA + sb + d0, A + (size_t)r0c * DD + p * 16 + c0c * 4);
        CP16(aA + sb + d1, A + (size_t)r1c * DD + p * 16 + c1c * 4);
        CP16(aB + sb + d0, Bm + (size_t)r0c * DD + p * 16 + c0c * 4);
        CP16(aB + sb + d1, Bm + (size_t)r1c * DD + p * 16 + c1c * 4);
        CP_COMMIT();
    }

    const int NKT = DD / 16;                  // 32
    for (int kt = 0; kt < NKT; kt++) {
        CP_WAIT2();
        __syncthreads();

        if (kt + 3 < NKT) {
            int p = kt + 3;
            uint32_t sb = (uint32_t)(p & 3) * (STAGE_F * 4);
            CP16(aA + sb + d0, A + (size_t)r0c * DD + p * 16 + c0c * 4);
            CP16(aA + sb + d1, A + (size_t)r1c * DD + p * 16 + c1c * 4);
            CP16(aB + sb + d0, Bm + (size_t)r0c * DD + p * 16 + c0c * 4);
            CP16(aB + sb + d1, Bm + (size_t)r1c * DD + p * 16 + c1c * 4);
        }
        CP_COMMIT();

        const float* as = AsB + (kt & 3) * STAGE_F;
        const float* bs = BsB + (kt & 3) * STAGE_F;

        float4 pa[2][2];
#pragma unroll
        for (int mt = 0; mt < 2; mt++) {
            int rb = wm * 32 + mt * 16 + gid;
            pa[mt][0] = *(const float4*)(as + rb * ROWSTR + 4 * tq);
            pa[mt][1] = *(const float4*)(as + (rb + 8) * ROWSTR + 4 * tq);
        }
#pragma unroll
        for (int bg = 0; bg < 2; bg++) {
            float4 pb[4];
#pragma unroll
            for (int jj = 0; jj < 4; jj++) {
                int nb = wn * 64 + (bg * 4 + jj) * 8 + gid;
                pb[jj] = *(const float4*)(bs + nb * ROWSTR + 4 * tq);
            }
#pragma unroll
            for (int mt = 0; mt < 2; mt++)
#pragma unroll
                for (int jj = 0; jj < 4; jj++) {
                    int nt = bg * 4 + jj;
                    mma_tf32(acc[mt][nt],
                             __float_as_uint(pa[mt][0].x), __float_as_uint(pa[mt][1].x),
                             __float_as_uint(pa[mt][0].y), __float_as_uint(pa[mt][1].y),
                             __float_as_uint(pb[jj].x), __float_as_uint(pb[jj].y));
                    mma_tf32(acc[mt][nt],
                             __float_as_uint(pa[mt][0].z), __float_as_uint(pa[mt][1].z),
                             __float_as_uint(pa[mt][0].w), __float_as_uint(pa[mt][1].w),
                             __float_as_uint(pb[jj].z), __float_as_uint(pb[jj].w));
                }
        }
    }

#pragma unroll
    for (int mt = 0; mt < 2; mt++) {
        int r0g = row0 + wm * 32 + mt * 16 + gid;
        int r1g = r0g + 8;
#pragma unroll
        for (int nt = 0; nt < 8; nt++) {
            int col = col0 + wn * 64 + nt * 8 + 2 * tq;
            float2 bias = *(const float2*)(bc + col);
            float2 v0, v1;
            if (r0g < nw) {
                v0.x = acc[mt][nt][0] + bias.x;
                v0.y = acc[mt][nt][1] + bias.y;
            } else { v0.x = 0.f; v0.y = 0.f; }
            if (r1g < nw) {
                v1.x = acc[mt][nt][2] + bias.x;
                v1.y = acc[mt][nt][3] + bias.y;
            } else { v1.x = 0.f; v1.y = 0.f; }
            *(float2*)(outbase + (size_t)r0g * DD + col) = v0;
            *(float2*)(outbase + (size_t)r1g * DD + col) = v1;
        }
    }
}

// ---------------- launcher ----------------
extern "C" void kernel_launch(void* const* d_in, const int* in_sizes, int n_in,
                              void* d_out, int out_size) {
    const float* frame  = (const float*)d_in[0];   // [B,S,D]
    const float* wscore = (const float*)d_in[1];   // [2D,1]
    const float* bscore = (const float*)d_in[2];   // [1]
    const float* wcomb  = (const float*)d_in[3];   // [D,D]
    const float* bcomb  = (const float*)d_in[4];   // [D]
    float* out = (float*)d_out;

    float* tail = (out_size >= BB * SS * DD + BB) ? out + (size_t)BB * SS * DD : nullptr;

    const int SMEM_DYN = 2 * NST * STAGE_F * 4;    // 64 KB
    cudaFuncSetAttribute(k_gemm_tc, cudaFuncAttributeMaxDynamicSharedMemorySize, SMEM_DYN);

    k_prep<<<256 + (BB * SS) / 16, 256>>>(frame, wscore, wcomb);
    k_scan<<<BB, 1024>>>(bscore, tail);
    k_mean<<<(BB * SS) / 8, 256>>>(frame);
    dim3 grid(DD / 128, SS / 128, BB);
    k_gemm_tc<<<grid, 256, SMEM_DYN>>>(bcomb, out);
}